// round 14
// baseline (speedup 1.0000x reference)
#include <cuda_runtime.h>

// SSIM loss: B=64, C=1, H=W=512, 11x11 uniform box (1/121), SAME zero padding.
// out = 1 - mean( ret * cs ).
//
// Rotation trick: u=x+y, v=x-y; U=box(u), V=box(v), Su=box(u^2), Sv=box(v^2).
// Per-WARP private staging: each warp stages its own 128-col + halo span
// (36 uint4 of bf16x2 (u,v) pairs) in its own smem region -> the row loop
// needs only __syncwarp(), never __syncthreads(). Ring slices are
// thread-private (no sync). Horizontal 11-tap sums in native bf16x2;
// PRMT transpose to column-pair-major; SSIM epilogue in packed f32x2;
// vertical sums f32x2 with exact telescoping (masked bf16 unpack - unbiased).
//
// Block = one 64-row strip (512 blocks, 1 wave @ 4 blocks/SM); thread = 4 cols.
// smem = 36864 (ring) + 9472 (4 warps x 2 bufs x 2 rows x 37 uint4) = 46336.

#define WID    512
#define HEI    512
#define RH     64
#define TPB    128
#define NBLK   512
#define NSLOT  9
#define WREG   37                                     // uint4 per warp row span
#define RING_BYTES  (NSLOT * 2 * TPB * 16)            // 36864
#define STAGE_OFF   RING_BYTES
#define SMEM_BYTES  (STAGE_OFF + 4 * 4 * WREG * 16)   // + 9472 = 46336

typedef unsigned long long u64;

__device__ float    g_part[NBLK];
__device__ unsigned g_cnt;

// ---- f32x2 packed helpers ----
__device__ __forceinline__ u64 pk2(float lo, float hi) {
    u64 r; asm("mov.b64 %0,{%1,%2};" : "=l"(r) : "f"(lo), "f"(hi)); return r;
}
__device__ __forceinline__ float2 upk(u64 a) {
    float2 v; asm("mov.b64 {%0,%1},%2;" : "=f"(v.x), "=f"(v.y) : "l"(a)); return v;
}
__device__ __forceinline__ u64 add2(u64 a, u64 b) {
    u64 r; asm("add.rn.f32x2 %0,%1,%2;" : "=l"(r) : "l"(a), "l"(b)); return r;
}
__device__ __forceinline__ u64 mul2(u64 a, u64 b) {
    u64 r; asm("mul.rn.f32x2 %0,%1,%2;" : "=l"(r) : "l"(a), "l"(b)); return r;
}
__device__ __forceinline__ u64 fma2(u64 a, u64 b, u64 c) {
    u64 r; asm("fma.rn.f32x2 %0,%1,%2,%3;" : "=l"(r) : "l"(a), "l"(b), "l"(c)); return r;
}
#define NEG1_PAIR 0xBF800000BF800000ull
__device__ __forceinline__ u64 sub2(u64 a, u64 b) { return fma2(b, NEG1_PAIR, a); }

// ---- bf16x2 helpers ----
__device__ __forceinline__ unsigned pkbf(float lo, float hi) {
    unsigned r; asm("cvt.rn.bf16x2.f32 %0,%1,%2;" : "=r"(r) : "f"(hi), "f"(lo)); return r;
}
// masked unpack (UNBIASED - the junk-tail variant shifts the mean)
__device__ __forceinline__ u64 upbf(unsigned v) {
    unsigned lo = v << 16, hi = v & 0xffff0000u;
    u64 r; asm("mov.b64 %0,{%1,%2};" : "=l"(r) : "r"(lo), "r"(hi)); return r;
}
__device__ __forceinline__ unsigned badd(unsigned a, unsigned b) {
    unsigned r; asm("add.rn.bf16x2 %0,%1,%2;" : "=r"(r) : "r"(a), "r"(b)); return r;
}
__device__ __forceinline__ unsigned bsub(unsigned a, unsigned b) {
    unsigned r; asm("sub.rn.bf16x2 %0,%1,%2;" : "=r"(r) : "r"(a), "r"(b)); return r;
}
__device__ __forceinline__ unsigned bmul(unsigned a, unsigned b) {
    unsigned r; asm("mul.rn.bf16x2 %0,%1,%2;" : "=r"(r) : "r"(a), "r"(b)); return r;
}
__device__ __forceinline__ unsigned bfma(unsigned a, unsigned b, unsigned c) {
    unsigned r; asm("fma.rn.bf16x2 %0,%1,%2,%3;" : "=r"(r) : "r"(a), "r"(b), "r"(c)); return r;
}
__device__ __forceinline__ unsigned prmt(unsigned a, unsigned b, unsigned sel) {
    unsigned r; asm("prmt.b32 %0,%1,%2,%3;" : "=r"(r) : "r"(a), "r"(b), "r"(sel)); return r;
}

__global__ void __launch_bounds__(TPB, 4)
ssim_k(const float* __restrict__ img1, const float* __restrict__ img2,
       const float* __restrict__ window, float* __restrict__ out)
{
    extern __shared__ unsigned char smem_raw[];
    uint4* ring = (uint4*)smem_raw;                   // [slot][2][TPB] thread-private slices
    uint4* stg  = (uint4*)(smem_raw + STAGE_OFF);     // [warp][buf][row][WREG]

    const int h     = threadIdx.x;
    const int wp    = h >> 5;
    const int l     = h & 31;
    const int b     = blockIdx.x >> 3;
    const int strip = blockIdx.x & 7;
    const int r0    = strip * RH;

    const float w   = __ldg(window);      // 1/121
    const float hw  = 0.5f  * w;
    const float hw2 = 0.5f  * w * w;
    const float C1  = 1.6384f;
    const float C2  = 14.7456f;
    const u64 HWp   = pk2(hw, hw);
    const u64 HW2p  = pk2(hw2, hw2);
    const u64 NHW2p = pk2(-hw2, -hw2);
    const u64 C1p   = pk2(C1, C1);
    const u64 C2p   = pk2(C2, C2);

    const float* base1 = img1 + (size_t)b * (HEI * WID);
    const float* base2 = img2 + (size_t)b * (HEI * WID);

    uint4* wstg = stg + wp * (4 * WREG);

    // warp span: uint4 k covers cols 128*wp - 8 + 4k, k in [0,36)
    // main load k=l -> global float4 index h-2 ; extra (lanes 0-3) k=32+l ->
    // global float4 index 32*wp + 30 + l
    const bool mainv  = !(wp == 0 && l < 2);
    const bool xlane  = (l < 4);
    const bool extrav = (wp < 3) || (l < 2);
    const int  gx     = 32 * wp + 30 + l;

    const float4 z4 = make_float4(0.f, 0.f, 0.f, 0.f);
    const uint4  zu = make_uint4(0u, 0u, 0u, 0u);
    #pragma unroll
    for (int s = 0; s < 2 * NSLOT; s++) ring[s * TPB + h] = zu;

    // vertical sums, column-pair-major packed f32x2
    u64 VU[2]  = {0,0};
    u64 VVr[2] = {0,0};
    u64 VSu[2] = {0,0};
    u64 VSv[2] = {0,0};
    uint4 h0A = zu, h0B = zu;  // held h(r-2)
    uint4 h1A = zu, h1B = zu;  // held h(r-1)
    float acc = 0.f;
    int slot = 0;

    float4 pa0, pa1, pb0, pb1;
    float4 qa0, qa1, qb0, qb1;

    auto ldg2 = [&](int r) {
        bool v0 = ((unsigned)r       < (unsigned)HEI);
        bool v1 = ((unsigned)(r + 1) < (unsigned)HEI);
        const float4* q1 = (const float4*)(base1 + r * WID);
        const float4* q2 = (const float4*)(base2 + r * WID);
        const float4* q3 = (const float4*)(base1 + (r + 1) * WID);
        const float4* q4 = (const float4*)(base2 + (r + 1) * WID);
        pa0 = (v0 && mainv) ? __ldg(q1 + (h - 2)) : z4;
        pb0 = (v0 && mainv) ? __ldg(q2 + (h - 2)) : z4;
        qa0 = (v1 && mainv) ? __ldg(q3 + (h - 2)) : z4;
        qb0 = (v1 && mainv) ? __ldg(q4 + (h - 2)) : z4;
        if (xlane) {
            pa1 = (v0 && extrav) ? __ldg(q1 + gx) : z4;
            pb1 = (v0 && extrav) ? __ldg(q2 + gx) : z4;
            qa1 = (v1 && extrav) ? __ldg(q3 + gx) : z4;
            qb1 = (v1 && extrav) ? __ldg(q4 + gx) : z4;
        }
    };

    auto sts2 = [&](int buf) {
        uint4* ta = wstg + (buf * 2 + 0) * WREG;
        uint4* tb = wstg + (buf * 2 + 1) * WREG;
        ta[l] = make_uint4(pkbf(pa0.x + pb0.x, pa0.x - pb0.x),
                           pkbf(pa0.y + pb0.y, pa0.y - pb0.y),
                           pkbf(pa0.z + pb0.z, pa0.z - pb0.z),
                           pkbf(pa0.w + pb0.w, pa0.w - pb0.w));
        tb[l] = make_uint4(pkbf(qa0.x + qb0.x, qa0.x - qb0.x),
                           pkbf(qa0.y + qb0.y, qa0.y - qb0.y),
                           pkbf(qa0.z + qb0.z, qa0.z - qb0.z),
                           pkbf(qa0.w + qb0.w, qa0.w - qb0.w));
        if (xlane) {
            ta[32 + l] = make_uint4(pkbf(pa1.x + pb1.x, pa1.x - pb1.x),
                                    pkbf(pa1.y + pb1.y, pa1.y - pb1.y),
                                    pkbf(pa1.z + pb1.z, pa1.z - pb1.z),
                                    pkbf(pa1.w + pb1.w, pa1.w - pb1.w));
            tb[32 + l] = make_uint4(pkbf(qa1.x + qb1.x, qa1.x - qb1.x),
                                    pkbf(qa1.y + qb1.y, qa1.y - qb1.y),
                                    pkbf(qa1.z + qb1.z, qa1.z - qb1.z),
                                    pkbf(qa1.w + qb1.w, qa1.w - qb1.w));
        }
    };

    auto process = [&](int buf, int row, bool emit) {
        const uint4* t = wstg + (buf * 2 + row) * WREG;
        uint4 w0 = t[l], w1 = t[l+1], w2 = t[l+2], w3 = t[l+3], w4 = t[l+4];
        unsigned sd[20] = { w0.x, w0.y, w0.z, w0.w,  w1.x, w1.y, w1.z, w1.w,
                            w2.x, w2.y, w2.z, w2.w,  w3.x, w3.y, w3.z, w3.w,
                            w4.x, w4.y, w4.z, w4.w };
        // sd[m] = (u,v) bf16x2 at column 4h-8+m ; window for col j: m in [3+j, 13+j]

        // ---- linear stream (U, V) in native bf16x2 ----
        unsigned L0, L1, L2, L3;
        {
            unsigned p01 = badd(sd[3], sd[4]),  p23 = badd(sd[5], sd[6]);
            unsigned p45 = badd(sd[7], sd[8]),  p67 = badd(sd[9], sd[10]);
            unsigned p89 = badd(sd[11], sd[12]);
            L0 = badd(badd(badd(p01, p23), badd(p45, p67)), badd(p89, sd[13]));
            unsigned dA = bsub(sd[14], sd[3]);
            unsigned dB = bsub(sd[15], sd[4]);
            unsigned dC = bsub(sd[16], sd[5]);
            L1 = badd(L0, dA);
            L2 = badd(L1, dB);
            L3 = badd(L2, dC);
        }

        // ---- square stream (Su, Sv) in native bf16x2 ----
        unsigned S0, S1, S2, S3;
        {
            unsigned q3 = bmul(sd[3], sd[3]);
            unsigned cA = q3;
            cA = bfma(sd[4], sd[4], cA); cA = bfma(sd[5], sd[5], cA);
            cA = bfma(sd[6], sd[6], cA); cA = bfma(sd[7], sd[7], cA);
            cA = bfma(sd[8], sd[8], cA);
            unsigned cB = bmul(sd[9], sd[9]);
            cB = bfma(sd[10], sd[10], cB); cB = bfma(sd[11], sd[11], cB);
            cB = bfma(sd[12], sd[12], cB); cB = bfma(sd[13], sd[13], cB);
            S0 = badd(cA, cB);
            unsigned q4 = bmul(sd[4], sd[4]);
            unsigned q5 = bmul(sd[5], sd[5]);
            unsigned v1 = bsub(bmul(sd[14], sd[14]), q3);
            unsigned v2 = bsub(bmul(sd[15], sd[15]), q4);
            unsigned v3 = bsub(bmul(sd[16], sd[16]), q5);
            S1 = badd(S0, v1);
            S2 = badd(S1, v2);
            S3 = badd(S2, v3);
        }

        // ---- transpose to column-pair-major ----
        uint4 nA = make_uint4(prmt(L0, L1, 0x5410), prmt(L0, L1, 0x7632),
                              prmt(L2, L3, 0x5410), prmt(L2, L3, 0x7632));
        uint4 nB = make_uint4(prmt(S0, S1, 0x5410), prmt(S0, S1, 0x7632),
                              prmt(S2, S3, 0x5410), prmt(S2, S3, 0x7632));

        // ---- ring (thread-private slice): read h(r-11); write held h(r-2) ----
        uint4* rp = ring + slot * (2 * TPB) + h;
        uint4 oA = rp[0];
        uint4 oB = rp[TPB];
        rp[0] = h0A; rp[TPB] = h0B;
        h0A = h1A; h0B = h1B;
        h1A = nA;  h1B = nB;
        VU[0]  = add2(VU[0],  sub2(upbf(nA.x), upbf(oA.x)));
        VVr[0] = add2(VVr[0], sub2(upbf(nA.y), upbf(oA.y)));
        VU[1]  = add2(VU[1],  sub2(upbf(nA.z), upbf(oA.z)));
        VVr[1] = add2(VVr[1], sub2(upbf(nA.w), upbf(oA.w)));
        VSu[0] = add2(VSu[0], sub2(upbf(nB.x), upbf(oB.x)));
        VSv[0] = add2(VSv[0], sub2(upbf(nB.y), upbf(oB.y)));
        VSu[1] = add2(VSu[1], sub2(upbf(nB.z), upbf(oB.z)));
        VSv[1] = add2(VSv[1], sub2(upbf(nB.w), upbf(oB.w)));
        slot = (slot == NSLOT - 1) ? 0 : slot + 1;

        if (emit) {
            float Nv[4], Dv[4];
            #pragma unroll
            for (int p = 0; p < 2; p++) {
                u64 U2 = mul2(VU[p],  VU[p]);
                u64 V2 = mul2(VVr[p], VVr[p]);
                u64 du = sub2(U2, V2), su = add2(U2, V2);
                u64 dm = sub2(VSu[p], VSv[p]), sp = add2(VSu[p], VSv[p]);
                u64 n1 = fma2(HW2p, du, C1p);
                u64 d1 = fma2(HW2p, su, C1p);
                u64 n2 = fma2(HWp, dm, fma2(NHW2p, du, C2p));
                u64 d2 = fma2(HWp, sp, fma2(NHW2p, su, C2p));
                float2 Np = upk(mul2(n1, n2));
                float2 Dp = upk(mul2(d1, d2));
                Nv[2*p] = Np.x; Nv[2*p+1] = Np.y;
                Dv[2*p] = Dp.x; Dv[2*p+1] = Dp.y;
            }
            acc += __fdividef(fmaf(Nv[0], Dv[1], Nv[1] * Dv[0]), Dv[0] * Dv[1]);
            acc += __fdividef(fmaf(Nv[2], Dv[3], Nv[3] * Dv[2]), Dv[2] * Dv[3]);
        }
    };

    // ---- warp-independent pipeline: 74 rows in 37 two-row iterations.
    // 2 warp-private buffers; same-warp program order + one __syncwarp per
    // iteration gives all cross-lane write->read / read->rewrite ordering.
    const int q = r0 - 5;
    ldg2(q);
    sts2(0);
    __syncwarp();

    #pragma unroll 2
    for (int i = 0; i < 37; ++i) {
        bool emit = (i >= 5);
        if (i != 36) ldg2(q + 2 * (i + 1));
        process(i & 1, 0, emit);
        process(i & 1, 1, emit);
        if (i != 36) { sts2((i + 1) & 1); __syncwarp(); }
    }

    // ---- block reduction + last-block finish ----
    #pragma unroll
    for (int o = 16; o > 0; o >>= 1)
        acc += __shfl_xor_sync(0xffffffffu, acc, o);
    __shared__ float wsum[4];
    __shared__ int lastflag;
    if (l == 0) wsum[wp] = acc;
    __syncthreads();
    if (h == 0) {
        float bs = (wsum[0] + wsum[1]) + (wsum[2] + wsum[3]);
        g_part[blockIdx.x] = bs;
        __threadfence();
        unsigned t = atomicAdd(&g_cnt, 1u);
        lastflag = (t == NBLK - 1) ? 1 : 0;
    }
    __syncthreads();

    if (lastflag) {
        volatile float* vp = g_part;
        double d = 0.0;
        #pragma unroll
        for (int k = 0; k < NBLK / TPB; ++k)
            d += (double)vp[h + k * TPB];
        #pragma unroll
        for (int o = 16; o > 0; o >>= 1)
            d += __shfl_xor_sync(0xffffffffu, d, o);
        __shared__ double dsum[4];
        if (l == 0) dsum[wp] = d;
        __syncthreads();
        if (h == 0) {
            double tot = (dsum[0] + dsum[1]) + (dsum[2] + dsum[3]);
            out[0] = (float)(1.0 - tot * (1.0 / 16777216.0));
            g_cnt = 0;
        }
    }
}

extern "C" void kernel_launch(void* const* d_in, const int* in_sizes, int n_in,
                              void* d_out, int out_size)
{
    const float* img1   = (const float*)d_in[0];
    const float* img2   = (const float*)d_in[1];
    const float* window = (const float*)d_in[2];
    (void)in_sizes; (void)n_in; (void)out_size;

    cudaFuncSetAttribute(ssim_k,
                         cudaFuncAttributeMaxDynamicSharedMemorySize, SMEM_BYTES);
    ssim_k<<<NBLK, TPB, SMEM_BYTES>>>(img1, img2, window, (float*)d_out);
}

// round 15
// speedup vs baseline: 1.0387x; 1.0387x over previous
#include <cuda_runtime.h>

// SSIM loss: B=64, C=1, H=W=512, 11x11 uniform box (1/121), SAME zero padding.
// out = 1 - mean( ret * cs ).
//
// Rotation trick: u=x+y, v=x-y; U=box(u), V=box(v), Su=box(u^2), Sv=box(v^2).
// Per-WARP private staging (loop uses only __syncwarp); horizontal 11-tap sums
// in native bf16x2; PRMT transpose to column-pair-major; SSIM epilogue packed
// f32x2; vertical sums f32x2, exact telescoping (masked bf16 unpack, unbiased).
//
// GRID BALANCE: 9 strips per image (heights 58x8 + 48) -> 576 blocks.
// 148 SMs @ 4 blocks/SM: makespan 4*(58+10)=272 row-units vs 4*74=296 for the
// old 8x64 split (512 blocks left 80 SMs with only 3 blocks).
// smem = 36864 (ring) + 9472 (warp staging) = 46336 -> 4 blocks/SM.

#define WID    512
#define HEI    512
#define TPB    128
#define SPI    9                                      // strips per image
#define RH_MAIN 58
#define NBLK   (64 * SPI)                             // 576
#define NSLOT  9
#define WREG   37
#define RING_BYTES  (NSLOT * 2 * TPB * 16)            // 36864
#define STAGE_OFF   RING_BYTES
#define SMEM_BYTES  (STAGE_OFF + 4 * 4 * WREG * 16)   // + 9472 = 46336

typedef unsigned long long u64;

__device__ float    g_part[NBLK];
__device__ unsigned g_cnt;

// ---- f32x2 packed helpers ----
__device__ __forceinline__ u64 pk2(float lo, float hi) {
    u64 r; asm("mov.b64 %0,{%1,%2};" : "=l"(r) : "f"(lo), "f"(hi)); return r;
}
__device__ __forceinline__ float2 upk(u64 a) {
    float2 v; asm("mov.b64 {%0,%1},%2;" : "=f"(v.x), "=f"(v.y) : "l"(a)); return v;
}
__device__ __forceinline__ u64 add2(u64 a, u64 b) {
    u64 r; asm("add.rn.f32x2 %0,%1,%2;" : "=l"(r) : "l"(a), "l"(b)); return r;
}
__device__ __forceinline__ u64 mul2(u64 a, u64 b) {
    u64 r; asm("mul.rn.f32x2 %0,%1,%2;" : "=l"(r) : "l"(a), "l"(b)); return r;
}
__device__ __forceinline__ u64 fma2(u64 a, u64 b, u64 c) {
    u64 r; asm("fma.rn.f32x2 %0,%1,%2,%3;" : "=l"(r) : "l"(a), "l"(b), "l"(c)); return r;
}
#define NEG1_PAIR 0xBF800000BF800000ull
__device__ __forceinline__ u64 sub2(u64 a, u64 b) { return fma2(b, NEG1_PAIR, a); }

// ---- bf16x2 helpers ----
__device__ __forceinline__ unsigned pkbf(float lo, float hi) {
    unsigned r; asm("cvt.rn.bf16x2.f32 %0,%1,%2;" : "=r"(r) : "f"(hi), "f"(lo)); return r;
}
// masked unpack (UNBIASED)
__device__ __forceinline__ u64 upbf(unsigned v) {
    unsigned lo = v << 16, hi = v & 0xffff0000u;
    u64 r; asm("mov.b64 %0,{%1,%2};" : "=l"(r) : "r"(lo), "r"(hi)); return r;
}
__device__ __forceinline__ unsigned badd(unsigned a, unsigned b) {
    unsigned r; asm("add.rn.bf16x2 %0,%1,%2;" : "=r"(r) : "r"(a), "r"(b)); return r;
}
__device__ __forceinline__ unsigned bsub(unsigned a, unsigned b) {
    unsigned r; asm("sub.rn.bf16x2 %0,%1,%2;" : "=r"(r) : "r"(a), "r"(b)); return r;
}
__device__ __forceinline__ unsigned bmul(unsigned a, unsigned b) {
    unsigned r; asm("mul.rn.bf16x2 %0,%1,%2;" : "=r"(r) : "r"(a), "r"(b)); return r;
}
__device__ __forceinline__ unsigned bfma(unsigned a, unsigned b, unsigned c) {
    unsigned r; asm("fma.rn.bf16x2 %0,%1,%2,%3;" : "=r"(r) : "r"(a), "r"(b), "r"(c)); return r;
}
__device__ __forceinline__ unsigned prmt(unsigned a, unsigned b, unsigned sel) {
    unsigned r; asm("prmt.b32 %0,%1,%2,%3;" : "=r"(r) : "r"(a), "r"(b), "r"(sel)); return r;
}

__global__ void __launch_bounds__(TPB, 4)
ssim_k(const float* __restrict__ img1, const float* __restrict__ img2,
       const float* __restrict__ window, float* __restrict__ out)
{
    extern __shared__ unsigned char smem_raw[];
    uint4* ring = (uint4*)smem_raw;                   // [slot][2][TPB]
    uint4* stg  = (uint4*)(smem_raw + STAGE_OFF);     // [warp][buf][row][WREG]

    const int h     = threadIdx.x;
    const int wp    = h >> 5;
    const int l     = h & 31;
    const int bid   = blockIdx.x;
    const int b     = bid / SPI;
    const int strip = bid - b * SPI;
    const int r0    = strip * RH_MAIN;
    const int nit   = (strip == SPI - 1) ? (48 + 10) / 2 : (RH_MAIN + 10) / 2;

    const float w   = __ldg(window);      // 1/121
    const float hw  = 0.5f  * w;
    const float hw2 = 0.5f  * w * w;
    const float C1  = 1.6384f;
    const float C2  = 14.7456f;
    const u64 HWp   = pk2(hw, hw);
    const u64 HW2p  = pk2(hw2, hw2);
    const u64 NHW2p = pk2(-hw2, -hw2);
    const u64 C1p   = pk2(C1, C1);
    const u64 C2p   = pk2(C2, C2);

    const float* base1 = img1 + (size_t)b * (HEI * WID);
    const float* base2 = img2 + (size_t)b * (HEI * WID);

    uint4* wstg = stg + wp * (4 * WREG);

    const bool mainv  = !(wp == 0 && l < 2);
    const bool xlane  = (l < 4);
    const bool extrav = (wp < 3) || (l < 2);
    const int  gx     = 32 * wp + 30 + l;

    const float4 z4 = make_float4(0.f, 0.f, 0.f, 0.f);
    const uint4  zu = make_uint4(0u, 0u, 0u, 0u);
    #pragma unroll
    for (int s = 0; s < 2 * NSLOT; s++) ring[s * TPB + h] = zu;

    u64 VU[2]  = {0,0};
    u64 VVr[2] = {0,0};
    u64 VSu[2] = {0,0};
    u64 VSv[2] = {0,0};
    uint4 h0A = zu, h0B = zu;  // held h(r-2)
    uint4 h1A = zu, h1B = zu;  // held h(r-1)
    float acc = 0.f;
    int slot = 0;

    float4 pa0, pa1, pb0, pb1;
    float4 qa0, qa1, qb0, qb1;

    auto ldg2 = [&](int r) {
        bool v0 = ((unsigned)r       < (unsigned)HEI);
        bool v1 = ((unsigned)(r + 1) < (unsigned)HEI);
        const float4* q1 = (const float4*)(base1 + r * WID);
        const float4* q2 = (const float4*)(base2 + r * WID);
        const float4* q3 = (const float4*)(base1 + (r + 1) * WID);
        const float4* q4 = (const float4*)(base2 + (r + 1) * WID);
        pa0 = (v0 && mainv) ? __ldg(q1 + (h - 2)) : z4;
        pb0 = (v0 && mainv) ? __ldg(q2 + (h - 2)) : z4;
        qa0 = (v1 && mainv) ? __ldg(q3 + (h - 2)) : z4;
        qb0 = (v1 && mainv) ? __ldg(q4 + (h - 2)) : z4;
        if (xlane) {
            pa1 = (v0 && extrav) ? __ldg(q1 + gx) : z4;
            pb1 = (v0 && extrav) ? __ldg(q2 + gx) : z4;
            qa1 = (v1 && extrav) ? __ldg(q3 + gx) : z4;
            qb1 = (v1 && extrav) ? __ldg(q4 + gx) : z4;
        }
    };

    auto sts2 = [&](int buf) {
        uint4* ta = wstg + (buf * 2 + 0) * WREG;
        uint4* tb = wstg + (buf * 2 + 1) * WREG;
        ta[l] = make_uint4(pkbf(pa0.x + pb0.x, pa0.x - pb0.x),
                           pkbf(pa0.y + pb0.y, pa0.y - pb0.y),
                           pkbf(pa0.z + pb0.z, pa0.z - pb0.z),
                           pkbf(pa0.w + pb0.w, pa0.w - pb0.w));
        tb[l] = make_uint4(pkbf(qa0.x + qb0.x, qa0.x - qb0.x),
                           pkbf(qa0.y + qb0.y, qa0.y - qb0.y),
                           pkbf(qa0.z + qb0.z, qa0.z - qb0.z),
                           pkbf(qa0.w + qb0.w, qa0.w - qb0.w));
        if (xlane) {
            ta[32 + l] = make_uint4(pkbf(pa1.x + pb1.x, pa1.x - pb1.x),
                                    pkbf(pa1.y + pb1.y, pa1.y - pb1.y),
                                    pkbf(pa1.z + pb1.z, pa1.z - pb1.z),
                                    pkbf(pa1.w + pb1.w, pa1.w - pb1.w));
            tb[32 + l] = make_uint4(pkbf(qa1.x + qb1.x, qa1.x - qb1.x),
                                    pkbf(qa1.y + qb1.y, qa1.y - qb1.y),
                                    pkbf(qa1.z + qb1.z, qa1.z - qb1.z),
                                    pkbf(qa1.w + qb1.w, qa1.w - qb1.w));
        }
    };

    auto process = [&](int buf, int row, bool emit) {
        const uint4* t = wstg + (buf * 2 + row) * WREG;
        uint4 w0 = t[l], w1 = t[l+1], w2 = t[l+2], w3 = t[l+3], w4 = t[l+4];
        unsigned sd[20] = { w0.x, w0.y, w0.z, w0.w,  w1.x, w1.y, w1.z, w1.w,
                            w2.x, w2.y, w2.z, w2.w,  w3.x, w3.y, w3.z, w3.w,
                            w4.x, w4.y, w4.z, w4.w };

        // ---- linear stream (U, V) ----
        unsigned L0, L1, L2, L3;
        {
            unsigned p01 = badd(sd[3], sd[4]),  p23 = badd(sd[5], sd[6]);
            unsigned p45 = badd(sd[7], sd[8]),  p67 = badd(sd[9], sd[10]);
            unsigned p89 = badd(sd[11], sd[12]);
            L0 = badd(badd(badd(p01, p23), badd(p45, p67)), badd(p89, sd[13]));
            unsigned dA = bsub(sd[14], sd[3]);
            unsigned dB = bsub(sd[15], sd[4]);
            unsigned dC = bsub(sd[16], sd[5]);
            L1 = badd(L0, dA);
            L2 = badd(L1, dB);
            L3 = badd(L2, dC);
        }

        // ---- square stream (Su, Sv) ----
        unsigned S0, S1, S2, S3;
        {
            unsigned q3 = bmul(sd[3], sd[3]);
            unsigned cA = q3;
            cA = bfma(sd[4], sd[4], cA); cA = bfma(sd[5], sd[5], cA);
            cA = bfma(sd[6], sd[6], cA); cA = bfma(sd[7], sd[7], cA);
            cA = bfma(sd[8], sd[8], cA);
            unsigned cB = bmul(sd[9], sd[9]);
            cB = bfma(sd[10], sd[10], cB); cB = bfma(sd[11], sd[11], cB);
            cB = bfma(sd[12], sd[12], cB); cB = bfma(sd[13], sd[13], cB);
            S0 = badd(cA, cB);
            unsigned q4 = bmul(sd[4], sd[4]);
            unsigned q5 = bmul(sd[5], sd[5]);
            unsigned v1 = bsub(bmul(sd[14], sd[14]), q3);
            unsigned v2 = bsub(bmul(sd[15], sd[15]), q4);
            unsigned v3 = bsub(bmul(sd[16], sd[16]), q5);
            S1 = badd(S0, v1);
            S2 = badd(S1, v2);
            S3 = badd(S2, v3);
        }

        // ---- transpose to column-pair-major ----
        uint4 nA = make_uint4(prmt(L0, L1, 0x5410), prmt(L0, L1, 0x7632),
                              prmt(L2, L3, 0x5410), prmt(L2, L3, 0x7632));
        uint4 nB = make_uint4(prmt(S0, S1, 0x5410), prmt(S0, S1, 0x7632),
                              prmt(S2, S3, 0x5410), prmt(S2, S3, 0x7632));

        // ---- ring: read h(r-11); write held h(r-2); shift holds ----
        uint4* rp = ring + slot * (2 * TPB) + h;
        uint4 oA = rp[0];
        uint4 oB = rp[TPB];
        rp[0] = h0A; rp[TPB] = h0B;
        h0A = h1A; h0B = h1B;
        h1A = nA;  h1B = nB;
        VU[0]  = add2(VU[0],  sub2(upbf(nA.x), upbf(oA.x)));
        VVr[0] = add2(VVr[0], sub2(upbf(nA.y), upbf(oA.y)));
        VU[1]  = add2(VU[1],  sub2(upbf(nA.z), upbf(oA.z)));
        VVr[1] = add2(VVr[1], sub2(upbf(nA.w), upbf(oA.w)));
        VSu[0] = add2(VSu[0], sub2(upbf(nB.x), upbf(oB.x)));
        VSv[0] = add2(VSv[0], sub2(upbf(nB.y), upbf(oB.y)));
        VSu[1] = add2(VSu[1], sub2(upbf(nB.z), upbf(oB.z)));
        VSv[1] = add2(VSv[1], sub2(upbf(nB.w), upbf(oB.w)));
        slot = (slot == NSLOT - 1) ? 0 : slot + 1;

        if (emit) {
            float Nv[4], Dv[4];
            #pragma unroll
            for (int p = 0; p < 2; p++) {
                u64 U2 = mul2(VU[p],  VU[p]);
                u64 V2 = mul2(VVr[p], VVr[p]);
                u64 du = sub2(U2, V2), su = add2(U2, V2);
                u64 dm = sub2(VSu[p], VSv[p]), sp = add2(VSu[p], VSv[p]);
                u64 n1 = fma2(HW2p, du, C1p);
                u64 d1 = fma2(HW2p, su, C1p);
                u64 n2 = fma2(HWp, dm, fma2(NHW2p, du, C2p));
                u64 d2 = fma2(HWp, sp, fma2(NHW2p, su, C2p));
                float2 Np = upk(mul2(n1, n2));
                float2 Dp = upk(mul2(d1, d2));
                Nv[2*p] = Np.x; Nv[2*p+1] = Np.y;
                Dv[2*p] = Dp.x; Dv[2*p+1] = Dp.y;
            }
            acc += __fdividef(fmaf(Nv[0], Dv[1], Nv[1] * Dv[0]), Dv[0] * Dv[1]);
            acc += __fdividef(fmaf(Nv[2], Dv[3], Nv[3] * Dv[2]), Dv[2] * Dv[3]);
        }
    };

    // ---- warp-independent pipeline: (RH+10) rows in nit two-row iterations ----
    const int q = r0 - 5;
    ldg2(q);
    sts2(0);
    __syncwarp();

    #pragma unroll 2
    for (int i = 0; i < nit; ++i) {
        bool emit = (i >= 5);
        bool more = (i != nit - 1);
        if (more) ldg2(q + 2 * (i + 1));
        process(i & 1, 0, emit);
        process(i & 1, 1, emit);
        if (more) { sts2((i + 1) & 1); __syncwarp(); }
    }

    // ---- block reduction + last-block finish ----
    #pragma unroll
    for (int o = 16; o > 0; o >>= 1)
        acc += __shfl_xor_sync(0xffffffffu, acc, o);
    __shared__ float wsum[4];
    __shared__ int lastflag;
    if (l == 0) wsum[wp] = acc;
    __syncthreads();
    if (h == 0) {
        float bs = (wsum[0] + wsum[1]) + (wsum[2] + wsum[3]);
        g_part[bid] = bs;
        __threadfence();
        unsigned t = atomicAdd(&g_cnt, 1u);
        lastflag = (t == NBLK - 1) ? 1 : 0;
    }
    __syncthreads();

    if (lastflag) {
        volatile float* vp = g_part;
        double d = 0.0;
        #pragma unroll
        for (int k = 0; k < (NBLK + TPB - 1) / TPB; ++k) {
            int idx = h + k * TPB;
            if (idx < NBLK) d += (double)vp[idx];
        }
        #pragma unroll
        for (int o = 16; o > 0; o >>= 1)
            d += __shfl_xor_sync(0xffffffffu, d, o);
        __shared__ double dsum[4];
        if (l == 0) dsum[wp] = d;
        __syncthreads();
        if (h == 0) {
            double tot = (dsum[0] + dsum[1]) + (dsum[2] + dsum[3]);
            out[0] = (float)(1.0 - tot * (1.0 / 16777216.0));
            g_cnt = 0;
        }
    }
}

extern "C" void kernel_launch(void* const* d_in, const int* in_sizes, int n_in,
                              void* d_out, int out_size)
{
    const float* img1   = (const float*)d_in[0];
    const float* img2   = (const float*)d_in[1];
    const float* window = (const float*)d_in[2];
    (void)in_sizes; (void)n_in; (void)out_size;

    cudaFuncSetAttribute(ssim_k,
                         cudaFuncAttributeMaxDynamicSharedMemorySize, SMEM_BYTES);
    ssim_k<<<NBLK, TPB, SMEM_BYTES>>>(img1, img2, window, (float*)d_out);
}